// round 17
// baseline (speedup 1.0000x reference)
#include <cuda_runtime.h>
#include <cuda_fp16.h>
#include <math_constants.h>

// SparseSelfAttention: B=2,H=16,L=2048,D=64,BLK=32,NB=64 (causal band, window=8)
// tf32 QK (raw fp32 K via cp.async = RZ tf32) + fp16 PV (register-direct P).
// CTA = 256 thr = 128 q rows (4 q-blocks). Pipeline segments of TWO kv blocks:
// half the barriers, 2x compute per wait to hide prefetch latency.

#define HEADS 16
#define SEQ   2048
#define DIM   64
#define NB    64
#define BLK   32

#define NSTR  72
#define VPSTR 72
#define QSTR  68
#define LOG2E 1.4426950408889634f

// dynamic smem byte offsets
#define OFF_KR   0u        // float [2 stages][2 blocks][32*NSTR]  = 36864 B
#define OFF_VP   36864u    // u32   [2][2][16*VPSTR]               = 18432 B
#define OFF_KP   55296u    // float [2][2][32]                     =   512 B
#define OFF_LAY  55808u    // int   [4*64]                         =  1024 B
#define OFF_JL   56832u    // int   [64]
#define OFF_JC   57088u    // int
#define SMEM_TOT 57344
// qstage (u32[128*QSTR] = 34816 B) overlays offset 0 (dead before K staging)

__device__ __forceinline__ unsigned f2tf32(float f) {
    unsigned r; asm("cvt.rna.tf32.f32 %0, %1;" : "=r"(r) : "f"(f)); return r;
}
__device__ __forceinline__ float ex2(float x) {
    float r; asm("ex2.approx.ftz.f32 %0, %1;" : "=f"(r) : "f"(x)); return r;
}
__device__ __forceinline__ unsigned packh2(float lo, float hi) {
    __half2 h; h.x = __float2half_rn(lo); h.y = __float2half_rn(hi);
    return *reinterpret_cast<unsigned*>(&h);
}
__device__ __forceinline__ void mma_tf32(float c[4], const unsigned a[4], const unsigned b[2]) {
    asm volatile("mma.sync.aligned.m16n8k8.row.col.f32.tf32.tf32.f32 "
                 "{%0,%1,%2,%3}, {%4,%5,%6,%7}, {%8,%9}, {%0,%1,%2,%3};"
                 : "+f"(c[0]), "+f"(c[1]), "+f"(c[2]), "+f"(c[3])
                 : "r"(a[0]), "r"(a[1]), "r"(a[2]), "r"(a[3]), "r"(b[0]), "r"(b[1]));
}
__device__ __forceinline__ void mma_f16(float c[4], const unsigned a[4], const unsigned b[2]) {
    asm volatile("mma.sync.aligned.m16n8k16.row.col.f32.f16.f16.f32 "
                 "{%0,%1,%2,%3}, {%4,%5,%6,%7}, {%8,%9}, {%0,%1,%2,%3};"
                 : "+f"(c[0]), "+f"(c[1]), "+f"(c[2]), "+f"(c[3])
                 : "r"(a[0]), "r"(a[1]), "r"(a[2]), "r"(a[3]), "r"(b[0]), "r"(b[1]));
}
__device__ __forceinline__ unsigned smem_u32(const void* p) {
    unsigned a;
    asm("{ .reg .u64 t; cvta.to.shared.u64 t, %1; cvt.u32.u64 %0, t; }" : "=r"(a) : "l"(p));
    return a;
}
__device__ __forceinline__ void cp16(unsigned dst, const void* src) {
    asm volatile("cp.async.ca.shared.global [%0], [%1], 16;\n" :: "r"(dst), "l"(src));
}

// one kv-block compute: QK(4 chains) -> softmax -> PV, accumulating o / lsums
__device__ __forceinline__ void compute_block(
    const unsigned* __restrict__ Kw, const float* __restrict__ kpv,
    const unsigned* __restrict__ Vw, const unsigned qa[8][4],
    float o[8][4], float& lsum_lo, float& lsum_hi, int gid, int t4)
{
    float c[4][4];
    #pragma unroll
    for (int g = 0; g < 4; g++) {
        float2 kb = *reinterpret_cast<const float2*>(&kpv[g * 8 + 2 * t4]);
        c[g][0] = kb.x * LOG2E; c[g][1] = kb.y * LOG2E;
        c[g][2] = c[g][0];      c[g][3] = c[g][1];
    }
    #pragma unroll
    for (int kst = 0; kst < 8; kst++) {
        #pragma unroll
        for (int g = 0; g < 4; g++) {
            unsigned bb[2];
            bb[0] = Kw[(g * 8 + gid) * NSTR + kst * 8 + t4    ];
            bb[1] = Kw[(g * 8 + gid) * NSTR + kst * 8 + t4 + 4];
            mma_tf32(c[g], qa[kst], bb);
        }
    }
    unsigned pa[4][2];
    #pragma unroll
    for (int g = 0; g < 4; g++) {
        float p0 = ex2(c[g][0]);
        float p1 = ex2(c[g][1]);
        float p2 = ex2(c[g][2]);
        float p3 = ex2(c[g][3]);
        lsum_lo += p0 + p1;
        lsum_hi += p2 + p3;
        pa[g][0] = packh2(p0, p1);
        pa[g][1] = packh2(p2, p3);
    }
    #pragma unroll
    for (int nt2 = 0; nt2 < 8; nt2++) {
        #pragma unroll
        for (int kst = 0; kst < 2; kst++) {
            unsigned aa[4];
            aa[0] = pa[2 * kst    ][0];
            aa[1] = pa[2 * kst    ][1];
            aa[2] = pa[2 * kst + 1][0];
            aa[3] = pa[2 * kst + 1][1];
            unsigned bb[2];
            bb[0] = Vw[(8 * kst + t4    ) * VPSTR + nt2 * 8 + gid];
            bb[1] = Vw[(8 * kst + 4 + t4) * VPSTR + nt2 * 8 + gid];
            mma_f16(o[nt2], aa, bb);
        }
    }
}

__global__ __launch_bounds__(256, 2)
void sparse_attn_tc(const float* __restrict__ qg,
                    const float* __restrict__ kg,
                    const float* __restrict__ vg,
                    const float* __restrict__ kpm,
                    const int*   __restrict__ layout,
                    float* __restrict__ outg)
{
    extern __shared__ __align__(16) char dsm[];
    float*    KR     = reinterpret_cast<float*>(dsm + OFF_KR);
    unsigned* VPm    = reinterpret_cast<unsigned*>(dsm + OFF_VP);
    float*    KP     = reinterpret_cast<float*>(dsm + OFF_KP);
    int*      lay    = reinterpret_cast<int*>(dsm + OFF_LAY);
    int*      jlist  = reinterpret_cast<int*>(dsm + OFF_JL);
    int*      jcntp  = reinterpret_cast<int*>(dsm + OFF_JC);
    unsigned* qstage = reinterpret_cast<unsigned*>(dsm);

    const int tid  = threadIdx.x;
    const int w    = tid >> 5;
    const int lane = tid & 31;
    const int gid  = lane >> 2;
    const int t4   = lane & 3;

    const int i0 = blockIdx.x;
    const int h  = blockIdx.y;
    const int b  = blockIdx.z;
    const size_t bh = (size_t)b * HEADS + h;
    const float* kbase = kg + bh * SEQ * DIM;
    const float* vbase = vg + bh * SEQ * DIM;

    lay[tid] = layout[((size_t)h * NB + (i0 * 4 + (tid >> 6))) * NB + (tid & 63)];

    // ---- stage Q (tf32 RNA, scaled by 0.125*log2e) ----
    const float* qptr = qg + (bh * SEQ + (size_t)i0 * 128) * DIM;
    #pragma unroll
    for (int jj = 0; jj < 8; jj++) {
        int idx = tid + 256 * jj;
        int row = idx >> 4, d4 = idx & 15;
        float4 qv = reinterpret_cast<const float4*>(qptr)[idx];
        const float qs = 0.125f * LOG2E;
        uint4 t;
        t.x = f2tf32(qv.x * qs); t.y = f2tf32(qv.y * qs);
        t.z = f2tf32(qv.z * qs); t.w = f2tf32(qv.w * qs);
        *reinterpret_cast<uint4*>(&qstage[row * QSTR + d4 * 4]) = t;
    }
    __syncthreads();

    if (tid == 0) {
        int c = 0;
        for (int j = 0; j < NB; j++)
            if (lay[j] | lay[64 + j] | lay[128 + j] | lay[192 + j]) jlist[c++] = j;
        *jcntp = c;
    }

    // ---- Q A-fragments resident ----
    const int lrow = w * 16 + gid;
    unsigned qa[8][4];
    #pragma unroll
    for (int kst = 0; kst < 8; kst++) {
        qa[kst][0] = qstage[ lrow      * QSTR + kst * 8 + t4    ];
        qa[kst][1] = qstage[(lrow + 8) * QSTR + kst * 8 + t4    ];
        qa[kst][2] = qstage[ lrow      * QSTR + kst * 8 + t4 + 4];
        qa[kst][3] = qstage[(lrow + 8) * QSTR + kst * 8 + t4 + 4];
    }
    __syncthreads();   // qstage dead; KR/VP live; jlist visible

    const int nj = *jcntp;
    const int* layw = &lay[(w >> 1) * NB];
    const unsigned kr_base = smem_u32(KR);
    const unsigned kp_base = smem_u32(KP);
    const int krow = tid >> 4, kc4 = tid & 15;  // K cp.async + V ldg coords
    const int vpair = tid >> 4, vd4 = tid & 15;

    // slot helpers: slot index = stage*2 + blk
    #define KR_SLOT(sl)  (KR + (sl) * (BLK * NSTR))
    #define VP_SLOT(sl)  (VPm + (sl) * (16 * VPSTR))
    #define KP_SLOT(sl)  (KP + (sl) * BLK)

    // stage K + kpm for block j into slot sl via cp.async
    #define STAGE_K(sl, j) do { \
        const float* _kp = kbase + (size_t)(j) * BLK * DIM; \
        unsigned _so = kr_base + (unsigned)((sl) * BLK * NSTR * 4); \
        cp16(_so + (unsigned)((krow * NSTR + kc4 * 4) * 4), _kp + krow * DIM + kc4 * 4); \
        cp16(_so + (unsigned)(((krow + 16) * NSTR + kc4 * 4) * 4), _kp + (krow + 16) * DIM + kc4 * 4); \
    } while (0)

    // V for block j: LDG.128 x2 -> pack -> uint4 (landed later by caller)
    #define LDV(dst, j) do { \
        const float* _vp = vbase + (size_t)(j) * BLK * DIM; \
        float4 _e = reinterpret_cast<const float4*>(_vp)[(2 * vpair) * 16 + vd4]; \
        float4 _o = reinterpret_cast<const float4*>(_vp)[(2 * vpair + 1) * 16 + vd4]; \
        (dst).x = packh2(_e.x, _o.x); (dst).y = packh2(_e.y, _o.y); \
        (dst).z = packh2(_e.z, _o.z); (dst).w = packh2(_e.w, _o.w); \
    } while (0)

    #define STV(sl, v) \
        *reinterpret_cast<uint4*>(VP_SLOT(sl) + vpair * VPSTR + 4 * vd4) = (v)

    // kpm for segment (two blocks) via cp.async: tid<16 covers both
    #define STAGE_KPM(st, j0v, j1v, have1) do { \
        if (tid < 16) { \
            int _bs = tid >> 3, _t = tid & 7; \
            int _j = _bs ? (j1v) : (j0v); \
            if (_bs == 0 || (have1)) \
                cp16(kp_base + (unsigned)((((st) * 2 + _bs) * BLK + _t * 4) * 4), \
                     kpm + (size_t)b * SEQ + _j * BLK + _t * 4); \
        } \
    } while (0)

    // ---- prologue: stage segment 0 ----
    {
        int j0 = jlist[0];
        int have1 = nj > 1;
        int j1 = have1 ? jlist[1] : j0;
        STAGE_K(0, j0);
        if (have1) STAGE_K(1, j1);
        STAGE_KPM(0, j0, j1, have1);
        uint4 v0, v1;
        LDV(v0, j0);
        STV(0, v0);
        if (have1) { LDV(v1, j1); STV(1, v1); }
        asm volatile("cp.async.commit_group;\n" ::);
        asm volatile("cp.async.wait_group 0;\n" ::);
    }
    __syncthreads();

    float lsum_lo = 0.f, lsum_hi = 0.f;
    float o[8][4];
    #pragma unroll
    for (int n = 0; n < 8; n++) { o[n][0]=0.f; o[n][1]=0.f; o[n][2]=0.f; o[n][3]=0.f; }

    const int nseg = (nj + 1) >> 1;
    for (int sg = 0; sg < nseg; sg++) {
        const int s = sg & 1;

        // ---- prefetch segment sg+1 into stage s^1 ----
        uint4 pv0, pv1;
        int pf = 0;
        {
            int nb0 = 2 * (sg + 1);
            if (nb0 < nj) {
                int jn0 = jlist[nb0];
                int have1 = (nb0 + 1) < nj;
                int jn1 = have1 ? jlist[nb0 + 1] : jn0;
                STAGE_K((s ^ 1) * 2 + 0, jn0);
                if (have1) STAGE_K((s ^ 1) * 2 + 1, jn1);
                STAGE_KPM(s ^ 1, jn0, jn1, have1);
                LDV(pv0, jn0); pf = 1;
                if (have1) { LDV(pv1, jn1); pf = 3; }
            }
        }
        asm volatile("cp.async.commit_group;\n" ::);

        // ---- compute the two blocks of stage s ----
        {
            int j0 = jlist[2 * sg];
            if (layw[j0])
                compute_block(reinterpret_cast<const unsigned*>(KR_SLOT(s * 2)),
                              KP_SLOT(s * 2), VP_SLOT(s * 2),
                              qa, o, lsum_lo, lsum_hi, gid, t4);
            if (2 * sg + 1 < nj) {
                int j1 = jlist[2 * sg + 1];
                if (layw[j1])
                    compute_block(reinterpret_cast<const unsigned*>(KR_SLOT(s * 2 + 1)),
                                  KP_SLOT(s * 2 + 1), VP_SLOT(s * 2 + 1),
                                  qa, o, lsum_lo, lsum_hi, gid, t4);
            }
        }

        // ---- land prefetched V ----
        if (pf & 1) STV((s ^ 1) * 2 + 0, pv0);
        if (pf & 2) STV((s ^ 1) * 2 + 1, pv1);
        asm volatile("cp.async.wait_group 0;\n" ::);
        __syncthreads();
    }

    // ---- epilogue ----
    #pragma unroll
    for (int off = 1; off < 4; off <<= 1) {
        lsum_lo += __shfl_xor_sync(0xffffffffu, lsum_lo, off);
        lsum_hi += __shfl_xor_sync(0xffffffffu, lsum_hi, off);
    }
    float inv_lo = 1.0f / lsum_lo;
    float inv_hi = 1.0f / lsum_hi;
    float* op = outg + (bh * SEQ + (size_t)i0 * 128) * DIM;
    #pragma unroll
    for (int nt2 = 0; nt2 < 8; nt2++) {
        float2 vlo, vhi;
        vlo.x = o[nt2][0] * inv_lo; vlo.y = o[nt2][1] * inv_lo;
        vhi.x = o[nt2][2] * inv_hi; vhi.y = o[nt2][3] * inv_hi;
        reinterpret_cast<float2*>(op +  lrow      * DIM)[nt2 * 4 + t4] = vlo;
        reinterpret_cast<float2*>(op + (lrow + 8) * DIM)[nt2 * 4 + t4] = vhi;
    }
}

extern "C" void kernel_launch(void* const* d_in, const int* in_sizes, int n_in,
                              void* d_out, int out_size)
{
    const float* q   = (const float*)d_in[0];
    const float* k   = (const float*)d_in[1];
    const float* v   = (const float*)d_in[2];
    const float* kpmp = (const float*)d_in[3];
    const int* layout = (const int*)d_in[4];
    float* out = (float*)d_out;

    cudaFuncSetAttribute(sparse_attn_tc,
                         cudaFuncAttributeMaxDynamicSharedMemorySize, SMEM_TOT);
    dim3 grid(SEQ / 128, HEADS, 2);
    dim3 block(256);
    sparse_attn_tc<<<grid, block, SMEM_TOT>>>(q, k, v, kpmp, layout, out);
}